// round 2
// baseline (speedup 1.0000x reference)
#include <cuda_runtime.h>

// MaxPool2d: kernel=2, stride=2, padding=0
// Input:  (32, 64, 224, 224) fp32  -> NC = 2048 planes of 224x224
// Output: (32, 64, 112, 112) fp32
//
// Non-overlapping 2x2 windows: each input element read exactly once.
// Pure HBM-streaming kernel. Each thread: 4 x LDG.128 + 1 x STG.128,
// producing 4 output pixels from 16 input pixels.

#define IN_H   224
#define IN_W   224
#define OUT_H  112
#define OUT_W  112
#define NC     (32 * 64)

// Each thread handles 4 consecutive output columns (one float4 store).
// OUT_W / 4 = 28 float4-groups per output row.
#define OW4    (OUT_W / 4)
// total threads = NC * OUT_H * OW4 = 2048 * 112 * 28 = 6,422,528

__global__ __launch_bounds__(256)
void maxpool2d_k2s2_kernel(const float* __restrict__ in,
                           float* __restrict__ out)
{
    const long long idx = (long long)blockIdx.x * blockDim.x + threadIdx.x;
    const long long total = (long long)NC * OUT_H * OW4;
    if (idx >= total) return;

    const int ow4 = (int)(idx % OW4);            // which float4 group in output row
    const int oh  = (int)((idx / OW4) % OUT_H);  // output row
    const int nc  = (int)(idx / ((long long)OW4 * OUT_H));

    // Input base: plane + 2*oh row + 8*ow4 column
    const float* row0 = in + (long long)nc * (IN_H * IN_W) + (long long)(2 * oh) * IN_W + ow4 * 8;
    const float* row1 = row0 + IN_W;

    // 4 independent 128-bit loads (front-batched -> MLP=4)
    const float4 a0 = *reinterpret_cast<const float4*>(row0);
    const float4 a1 = *reinterpret_cast<const float4*>(row0 + 4);
    const float4 b0 = *reinterpret_cast<const float4*>(row1);
    const float4 b1 = *reinterpret_cast<const float4*>(row1 + 4);

    float4 o;
    o.x = fmaxf(fmaxf(a0.x, a0.y), fmaxf(b0.x, b0.y));
    o.y = fmaxf(fmaxf(a0.z, a0.w), fmaxf(b0.z, b0.w));
    o.z = fmaxf(fmaxf(a1.x, a1.y), fmaxf(b1.x, b1.y));
    o.w = fmaxf(fmaxf(a1.z, a1.w), fmaxf(b1.z, b1.w));

    float* outp = out + (long long)nc * (OUT_H * OUT_W) + (long long)oh * OUT_W + ow4 * 4;
    *reinterpret_cast<float4*>(outp) = o;
}

extern "C" void kernel_launch(void* const* d_in, const int* in_sizes, int n_in,
                              void* d_out, int out_size)
{
    const float* x = (const float*)d_in[0];
    float* y = (float*)d_out;

    const long long total = (long long)NC * OUT_H * OW4;  // 6,422,528
    const int block = 256;
    const long long grid = (total + block - 1) / block;   // 25088

    maxpool2d_k2s2_kernel<<<(unsigned)grid, block>>>(x, y);
}